// round 6
// baseline (speedup 1.0000x reference)
#include <cuda_runtime.h>
#include <math.h>
#include <stdint.h>

#define NTOK 32768
#define CCH  128
#define CF   512
#define NHEADS 8
#define HD   16
#define EPSF 1e-5f

// ---------------- scratch (device globals; no allocation allowed) ----------------
__device__ float g_xt[NTOK*CCH];    // x transposed to [N][C]
__device__ float g_q[NTOK*CCH];
__device__ float g_k[NTOK*CCH];
__device__ float g_v[NTOK*CCH];
__device__ float g_attn[NTOK*CCH];
__device__ float g_y[NTOK*CCH];     // proj out
__device__ float g_t[NTOK*CCH];     // instnorm1 out
__device__ float g_h1[NTOK*CF];     // ffn1 out
__device__ float g_u[NTOK*CCH];     // ffn2 + residual
__device__ float g_part[256*1024];  // [slot][block] partials
__device__ float g_stats[2*CCH];    // [c]=sum, [128+c]=sumsq

__device__ __forceinline__ uint32_t f2tf32(float f) {
    uint32_t u; asm("cvt.rna.tf32.f32 %0, %1;" : "=r"(u) : "f"(f)); return u;
}

__device__ __forceinline__ float gelu_tanh(float x) {
    const float c0 = 0.7978845608028654f;
    float x3 = x*x*x;
    return 0.5f*x*(1.0f + tanhf(c0*(x + 0.044715f*x3)));
}

__device__ __forceinline__ void mma_tf32(float c[4], const uint32_t a[4], const uint32_t b[2]) {
    asm volatile(
        "mma.sync.aligned.m16n8k8.row.col.f32.tf32.tf32.f32 "
        "{%0,%1,%2,%3}, {%4,%5,%6,%7}, {%8,%9}, {%0,%1,%2,%3};"
        : "+f"(c[0]), "+f"(c[1]), "+f"(c[2]), "+f"(c[3])
        : "r"(a[0]), "r"(a[1]), "r"(a[2]), "r"(a[3]), "r"(b[0]), "r"(b[1]));
}

// ---------------- transpose x [C][N] -> g_xt [N][C] ----------------
__global__ __launch_bounds__(256) void transpose_x(const float* __restrict__ x) {
    __shared__ float tile[32][33];
    const int n0 = blockIdx.x*32, c0 = blockIdx.y*32;
    const int tx = threadIdx.x & 31, ty = threadIdx.x >> 5;
#pragma unroll
    for (int r = 0; r < 32; r += 8)
        tile[ty+r][tx] = x[(size_t)(c0+ty+r)*NTOK + n0 + tx];
    __syncthreads();
#pragma unroll
    for (int r = 0; r < 32; r += 8)
        g_xt[(size_t)(n0+ty+r)*CCH + c0 + tx] = tile[tx][ty+r];
}

// ---------------- mma.sync tf32 GEMM ----------------
// out[n][o] = sum_k A[n][k] * W[o][k] (+bias, +epilogue)
// MODE 0: qkv  (A=g_xt, K=128, O=384 -> q/k/v scatter)
// MODE 1: proj (A=g_attn, K=128, O=128 -> g_y)
// MODE 2: ffn1 (A=g_t, K=128, O=512 -> g_h1, gelu)
// MODE 3: ffn2 (A=g_h1, K=512, O=128 -> g_u, +residual g_t)
//
// Block tile: 128(M) x 64(N), K-chunk 32. 8 warps: (wm 0..3) x (wn 0..1),
// warp tile 32x32 = 2 mtiles(16) x 4 ntiles(8). SMEM holds fragments in
// native mma layout so hot loop is LDS.128/LDS.64 only.
template<int KDIM, int MODE>
__global__ __launch_bounds__(256) void mma_gemm(const float* __restrict__ W,
                                                const float* __restrict__ bias) {
    __shared__ uint32_t As[4096];   // [mtile 8][kt 4][lane 32][reg 4]
    __shared__ uint32_t Bs[2048];   // [ntile 8][kt 4][lane 32][reg 2]

    const float* Ag = (MODE == 0) ? g_xt : (MODE == 1) ? g_attn : (MODE == 2) ? g_t : g_h1;

    const int n0 = blockIdx.x * 128;
    const int o0 = blockIdx.y * 64;
    const int tx = threadIdx.x;
    const int w  = tx >> 5, lane = tx & 31;
    const int wm = w >> 1, wn = w & 1;
    const int g  = lane >> 2, tq = lane & 3;

    float c[2][4][4];
#pragma unroll
    for (int mt = 0; mt < 2; mt++)
#pragma unroll
        for (int nt = 0; nt < 4; nt++)
#pragma unroll
            for (int i = 0; i < 4; i++) c[mt][nt][i] = 0.f;

    for (int kb = 0; kb < KDIM; kb += 32) {
        if (kb) __syncthreads();
        // stage A: 128 rows x 32 cols -> fragment layout
#pragma unroll
        for (int i = 0; i < 4; i++) {
            int L = i*256 + tx;
            int n = L >> 3, k4 = L & 7;
            float4 v = *(const float4*)&Ag[(size_t)(n0+n)*KDIM + kb + k4*4];
            int r = n & 15, mt = n >> 4, kt = k4 >> 1;
            int reg = (r >> 3) + 2*(k4 & 1);
            int base = ((mt*4 + kt)*32 + (r & 7)*4)*4 + reg;
            As[base+0]  = f2tf32(v.x);
            As[base+4]  = f2tf32(v.y);
            As[base+8]  = f2tf32(v.z);
            As[base+12] = f2tf32(v.w);
        }
        // stage B: 64 rows x 32 cols -> fragment layout
#pragma unroll
        for (int i = 0; i < 2; i++) {
            int L = i*256 + tx;
            int o = L >> 3, k4 = L & 7;
            float4 v = *(const float4*)&W[(size_t)(o0+o)*KDIM + kb + k4*4];
            int nn = o & 7, nt = o >> 3, kt = k4 >> 1, reg = k4 & 1;
            int base = ((nt*4 + kt)*32 + nn*4)*2 + reg;
            Bs[base+0] = f2tf32(v.x);
            Bs[base+2] = f2tf32(v.y);
            Bs[base+4] = f2tf32(v.z);
            Bs[base+6] = f2tf32(v.w);
        }
        __syncthreads();
#pragma unroll
        for (int kt = 0; kt < 4; kt++) {
            uint32_t a[2][4], b[4][2];
#pragma unroll
            for (int mt = 0; mt < 2; mt++) {
                uint4 av = *(const uint4*)&As[(((wm*2+mt)*4 + kt)*32 + lane)*4];
                a[mt][0] = av.x; a[mt][1] = av.y; a[mt][2] = av.z; a[mt][3] = av.w;
            }
#pragma unroll
            for (int nt = 0; nt < 4; nt++) {
                uint2 bv = *(const uint2*)&Bs[(((wn*4+nt)*4 + kt)*32 + lane)*2];
                b[nt][0] = bv.x; b[nt][1] = bv.y;
            }
#pragma unroll
            for (int mt = 0; mt < 2; mt++)
#pragma unroll
                for (int nt = 0; nt < 4; nt++)
                    mma_tf32(c[mt][nt], a[mt], b[nt]);
        }
    }

    // ---- epilogue ----
    float* dst; int ocol; int ostride;
    if (MODE == 0) {
        dst = (o0 < 128) ? g_q : (o0 < 256) ? g_k : g_v;
        ocol = o0 & 127; ostride = 128;
    } else if (MODE == 1) { dst = g_y;  ocol = o0; ostride = 128; }
    else if (MODE == 2)   { dst = g_h1; ocol = o0; ostride = 512; }
    else                  { dst = g_u;  ocol = o0; ostride = 128; }

#pragma unroll
    for (int mt = 0; mt < 2; mt++) {
#pragma unroll
        for (int nt = 0; nt < 4; nt++) {
            const int colb = (wn*4 + nt)*8 + tq*2;
            const float b0 = bias[o0 + colb];
            const float b1 = bias[o0 + colb + 1];
            const int row0 = n0 + (wm*2 + mt)*16 + g;
#pragma unroll
            for (int half = 0; half < 2; half++) {
                const int row = row0 + half*8;
                float v0 = c[mt][nt][half*2+0] + b0;
                float v1 = c[mt][nt][half*2+1] + b1;
                if (MODE == 2) { v0 = gelu_tanh(v0); v1 = gelu_tanh(v1); }
                else if (MODE == 3) {
                    const float2 r2 = *(const float2*)&g_t[(size_t)row*128 + o0 + colb];
                    v0 += r2.x; v1 += r2.y;
                }
                *(float2*)&dst[(size_t)row*ostride + ocol + colb] = make_float2(v0, v1);
            }
        }
    }
}

// ---------------- K2: neighborhood attention ----------------
__global__ __launch_bounds__(256) void attn_kernel(const float* __restrict__ rpb) {
    const int n = blockIdx.x;
    __shared__ int   s_nbr[27];
    __shared__ int   s_bidx[27];
    __shared__ float qs[NHEADS][HD];
    const int t = threadIdx.x;

    if (t < 27) {
        int hh = n >> 10, ww = (n >> 5) & 31, zz = n & 31;
        int sh = min(max(hh-1, 0), 29);
        int sw = min(max(ww-1, 0), 29);
        int sz = min(max(zz-1, 0), 29);
        int jh = t/9, jw = (t/3)%3, jz = t%3;
        s_nbr[t]  = (sh+jh)*1024 + (sw+jw)*32 + (sz+jz);
        int rh = sh+jh-hh+2, rw = sw+jw-ww+2, rz = sz+jz-zz+2;
        s_bidx[t] = (rh*5 + rw)*5 + rz;
    }
    if (t < 128) qs[t >> 4][t & 15] = g_q[(size_t)n*128 + t] * 0.25f;
    __syncthreads();

    const int h = t >> 5, lane = t & 31;
    float score = -1e30f;
    if (lane < 27) {
        int nb = s_nbr[lane];
        const float4* kp = (const float4*)&g_k[(size_t)nb*128 + h*16];
        float s = 0.f;
#pragma unroll
        for (int q4 = 0; q4 < 4; q4++) {
            float4 kv = kp[q4];
            s += qs[h][q4*4+0]*kv.x + qs[h][q4*4+1]*kv.y
               + qs[h][q4*4+2]*kv.z + qs[h][q4*4+3]*kv.w;
        }
        score = s + rpb[h*125 + s_bidx[lane]];
    }
    float mx = score;
#pragma unroll
    for (int off = 16; off; off >>= 1) mx = fmaxf(mx, __shfl_xor_sync(0xffffffffu, mx, off));
    float p = (lane < 27) ? __expf(score - mx) : 0.f;
    float sum = p;
#pragma unroll
    for (int off = 16; off; off >>= 1) sum += __shfl_xor_sync(0xffffffffu, sum, off);
    float inv = 1.f / sum;

    float acc = 0.f;
#pragma unroll 1
    for (int j = 0; j < 27; j++) {
        float pj = __shfl_sync(0xffffffffu, p, j);
        int nb = s_nbr[j];
        if (lane < 16) acc += pj * g_v[(size_t)nb*128 + h*16 + lane];
    }
    if (lane < 16) g_attn[(size_t)n*128 + h*16 + lane] = acc * inv;
}

// ---------------- instance-norm reductions (deterministic) ----------------
template<int MODE>  // 0: g_y, 1: g_u
__global__ __launch_bounds__(128) void reduce_partial() {
    const float* a = MODE ? g_u : g_y;
    const int c = threadIdx.x;
    const int b = blockIdx.x;              // 1024 blocks x 32 tokens
    const float* p = a + (size_t)b*32*128;
    float s = 0.f, s2 = 0.f;
#pragma unroll 8
    for (int i = 0; i < 32; i++) {
        float v = p[i*128 + c];
        s += v; s2 += v*v;
    }
    g_part[(size_t)c*1024 + b]       = s;
    g_part[(size_t)(128+c)*1024 + b] = s2;
}

__global__ __launch_bounds__(1024) void reduce_final() {
    __shared__ float red[1024];
    const int tid = threadIdx.x;
    const int slot = tid >> 2, part = tid & 3;
    const float4* p = (const float4*)&g_part[(size_t)slot*1024 + part*256];
    float s = 0.f;
#pragma unroll 8
    for (int i = 0; i < 64; i++) {
        float4 v = p[i];
        s += v.x + v.y + v.z + v.w;
    }
    red[tid] = s;
    __syncthreads();
    if (part == 0) g_stats[slot] = red[tid] + red[tid+1] + red[tid+2] + red[tid+3];
}

__global__ __launch_bounds__(256) void norm_apply() {
    const int idx = blockIdx.x*256 + threadIdx.x;
    const int c = idx & 127;
    float m   = g_stats[c]     * (1.0f/NTOK);
    float var = g_stats[c+128] * (1.0f/NTOK) - m*m;
    g_t[idx] = (g_y[idx] - m) * rsqrtf(var + EPSF);
}

__global__ __launch_bounds__(256) void norm_transpose(float* __restrict__ out) {
    __shared__ float tile[32][33];
    const int n0 = blockIdx.x*32, c0 = blockIdx.y*32;
    const int txx = threadIdx.x & 31, tyy = threadIdx.x >> 5;
    const int c = c0 + txx;
    float m   = g_stats[c]     * (1.0f/NTOK);
    float var = g_stats[c+128] * (1.0f/NTOK) - m*m;
    float rs  = rsqrtf(var + EPSF);
#pragma unroll
    for (int r = 0; r < 32; r += 8)
        tile[tyy+r][txx] = (g_u[(size_t)(n0+tyy+r)*128 + c] - m) * rs;
    __syncthreads();
#pragma unroll
    for (int r = 0; r < 32; r += 8)
        out[(size_t)(c0+tyy+r)*NTOK + n0 + txx] = tile[txx][tyy+r];
}

// ---------------- launch ----------------
extern "C" void kernel_launch(void* const* d_in, const int* in_sizes, int n_in,
                              void* d_out, int out_size) {
    const float* x      = (const float*)d_in[0];
    const float* w_qkv  = (const float*)d_in[1];
    const float* b_qkv  = (const float*)d_in[2];
    const float* rpb    = (const float*)d_in[3];
    const float* w_proj = (const float*)d_in[4];
    const float* b_proj = (const float*)d_in[5];
    const float* w_ffn1 = (const float*)d_in[6];
    const float* b_ffn1 = (const float*)d_in[7];
    const float* w_ffn2 = (const float*)d_in[8];
    const float* b_ffn2 = (const float*)d_in[9];
    float* out = (float*)d_out;

    transpose_x<<<dim3(NTOK/32, CCH/32), 256>>>(x);
    mma_gemm<128,0><<<dim3(NTOK/128, 6), 256>>>(w_qkv, b_qkv);
    attn_kernel<<<NTOK, 256>>>(rpb);
    mma_gemm<128,1><<<dim3(NTOK/128, 2), 256>>>(w_proj, b_proj);
    reduce_partial<0><<<1024, 128>>>();
    reduce_final<<<1, 1024>>>();
    norm_apply<<<NTOK*CCH/256, 256>>>();
    mma_gemm<128,2><<<dim3(NTOK/128, 8), 256>>>(w_ffn1, b_ffn1);
    mma_gemm<512,3><<<dim3(NTOK/128, 2), 256>>>(w_ffn2, b_ffn2);
    reduce_partial<1><<<1024, 128>>>();
    reduce_final<<<1, 1024>>>();
    norm_transpose<<<dim3(NTOK/32, CCH/32), 256>>>(out);
}

// round 7
// speedup vs baseline: 2.5916x; 2.5916x over previous
#include <cuda_runtime.h>
#include <math.h>
#include <stdint.h>

#define NTOK 32768
#define CCH  128
#define CF   512
#define NHEADS 8
#define HD   16
#define EPSF 1e-5f
#define INVN (1.0f/32768.0f)

// ---------------- scratch (device globals) ----------------
__device__ float g_xt[NTOK*CCH];        // x transposed to [N][C]
__device__ float g_q[NHEADS*NTOK*HD];   // [h][n][16]
__device__ float g_k[NHEADS*NTOK*HD];
__device__ float g_v[NHEADS*NTOK*HD];
__device__ float g_attn[NHEADS*NTOK*HD];// [h][n][16]
__device__ float g_y[NTOK*CCH];         // proj out [n][128]
__device__ float g_h1[NTOK*CF];         // ffn1 out [n][512]
__device__ float g_u[NTOK*CCH];         // ffn2 + residual [n][128]
__device__ float g_part[256*256];       // [mblock][slot]
__device__ float g_stats[2*CCH];        // [c]=sum, [128+c]=sumsq

__device__ __forceinline__ uint32_t f2tf32(float f) {
    uint32_t u; asm("cvt.rna.tf32.f32 %0, %1;" : "=r"(u) : "f"(f)); return u;
}
__device__ __forceinline__ float gelu_tanh(float x) {
    const float c0 = 0.7978845608028654f;
    float x3 = x*x*x;
    return 0.5f*x*(1.0f + tanhf(c0*(x + 0.044715f*x3)));
}
__device__ __forceinline__ void mma_tf32(float c[4], const uint32_t a[4], const uint32_t b[2]) {
    asm volatile(
        "mma.sync.aligned.m16n8k8.row.col.f32.tf32.tf32.f32 "
        "{%0,%1,%2,%3}, {%4,%5,%6,%7}, {%8,%9}, {%0,%1,%2,%3};"
        : "+f"(c[0]), "+f"(c[1]), "+f"(c[2]), "+f"(c[3])
        : "r"(a[0]), "r"(a[1]), "r"(a[2]), "r"(a[3]), "r"(b[0]), "r"(b[1]));
}

// ---------------- transpose x [C][N] -> g_xt [N][C] ----------------
__global__ __launch_bounds__(256) void transpose_x(const float* __restrict__ x) {
    __shared__ float tile[32][33];
    const int n0 = blockIdx.x*32, c0 = blockIdx.y*32;
    const int tx = threadIdx.x & 31, ty = threadIdx.x >> 5;
#pragma unroll
    for (int r = 0; r < 32; r += 8)
        tile[ty+r][tx] = x[(size_t)(c0+ty+r)*NTOK + n0 + tx];
    __syncthreads();
#pragma unroll
    for (int r = 0; r < 32; r += 8)
        g_xt[(size_t)(n0+ty+r)*CCH + c0 + tx] = tile[tx][ty+r];
}

// ---------------- mma.sync tf32 GEMM, conflict-free pad-36 smem ----------------
// MODE 0: qkv  (A=g_xt [n][128], O=384 -> q/k/v in [h][n][16])
// MODE 1: proj (A=g_attn gather [h][n][16], O=128 -> g_y; fused col partials)
// MODE 2: ffn1 (A=norm(g_y) on the fly, O=512 -> g_h1, gelu)
// MODE 3: ffn2 (A=g_h1 [n][512], O=128 -> g_u = +bias+norm(g_y) residual; fused partials)
// Block 128x64, 8 warps (wm 0..3)x(wn 0..1), warp tile 32x32.
template<int KDIM, int MODE>
__global__ __launch_bounds__(256) void mma_gemm(const float* __restrict__ W,
                                                const float* __restrict__ bias) {
    __shared__ uint32_t As[128*36];
    __shared__ uint32_t Bs[64*36];
    __shared__ float red[512];
    __shared__ float m_s[128], r_s[128];

    const int tx = threadIdx.x;
    const int w  = tx >> 5, lane = tx & 31;
    const int wm = w >> 1, wn = w & 1;
    const int g  = lane >> 2, tq = lane & 3;
    const int n0 = blockIdx.x * 128;
    const int o0 = blockIdx.y * 64;

    if (MODE == 2 || MODE == 3) {
        if (tx < 128) {
            float m = g_stats[tx] * INVN;
            float var = g_stats[128+tx] * INVN - m*m;
            m_s[tx] = m;
            r_s[tx] = rsqrtf(var + EPSF);
        }
        __syncthreads();
    }

    float c[2][4][4];
#pragma unroll
    for (int mt = 0; mt < 2; mt++)
#pragma unroll
        for (int nt = 0; nt < 4; nt++)
#pragma unroll
            for (int i = 0; i < 4; i++) c[mt][nt][i] = 0.f;

    for (int kb = 0; kb < KDIM; kb += 32) {
        // stage A: 128 rows x 32 cols
#pragma unroll
        for (int i = 0; i < 4; i++) {
            const int n  = i*32 + (tx >> 3);
            const int k4 = tx & 7;
            const int k  = kb + k4*4;
            float4 v;
            if (MODE == 0)
                v = *(const float4*)&g_xt[(size_t)(n0+n)*128 + k];
            else if (MODE == 1)
                v = *(const float4*)&g_attn[(size_t)(k>>4)*(NTOK*HD) + (size_t)(n0+n)*16 + (k&15)];
            else if (MODE == 2) {
                v = *(const float4*)&g_y[(size_t)(n0+n)*128 + k];
                v.x = (v.x - m_s[k+0]) * r_s[k+0];
                v.y = (v.y - m_s[k+1]) * r_s[k+1];
                v.z = (v.z - m_s[k+2]) * r_s[k+2];
                v.w = (v.w - m_s[k+3]) * r_s[k+3];
            } else
                v = *(const float4*)&g_h1[(size_t)(n0+n)*512 + k];
            uint4 u = make_uint4(f2tf32(v.x), f2tf32(v.y), f2tf32(v.z), f2tf32(v.w));
            *(uint4*)&As[n*36 + k4*4] = u;
        }
        // stage B: 64 rows x 32 cols
#pragma unroll
        for (int i = 0; i < 2; i++) {
            const int o  = i*32 + (tx >> 3);
            const int k4 = tx & 7;
            float4 v = *(const float4*)&W[(size_t)(o0+o)*KDIM + kb + k4*4];
            uint4 u = make_uint4(f2tf32(v.x), f2tf32(v.y), f2tf32(v.z), f2tf32(v.w));
            *(uint4*)&Bs[o*36 + k4*4] = u;
        }
        __syncthreads();
#pragma unroll
        for (int kt = 0; kt < 4; kt++) {
            const int kc = kt*8 + tq;
            uint32_t a[2][4], b[4][2];
#pragma unroll
            for (int mt = 0; mt < 2; mt++) {
                const int rb = (wm*32 + mt*16 + g)*36;
                a[mt][0] = As[rb + kc];
                a[mt][1] = As[rb + 8*36 + kc];
                a[mt][2] = As[rb + kc + 4];
                a[mt][3] = As[rb + 8*36 + kc + 4];
            }
#pragma unroll
            for (int nt = 0; nt < 4; nt++) {
                const int rb = ((wn*4+nt)*8 + g)*36;
                b[nt][0] = Bs[rb + kc];
                b[nt][1] = Bs[rb + kc + 4];
            }
#pragma unroll
            for (int mt = 0; mt < 2; mt++)
#pragma unroll
                for (int nt = 0; nt < 4; nt++)
                    mma_tf32(c[mt][nt], a[mt], b[nt]);
        }
        __syncthreads();
    }

    // ---- epilogue ----
    float s[4][2], q2[4][2];
    if (MODE == 1 || MODE == 3) {
#pragma unroll
        for (int nt = 0; nt < 4; nt++) { s[nt][0]=s[nt][1]=q2[nt][0]=q2[nt][1]=0.f; }
    }

#pragma unroll
    for (int mt = 0; mt < 2; mt++) {
#pragma unroll
        for (int nt = 0; nt < 4; nt++) {
            const int colb = (wn*4 + nt)*8 + tq*2;
            const float b0 = bias[o0 + colb];
            const float b1 = bias[o0 + colb + 1];
            const int row0 = n0 + (wm*2 + mt)*16 + g;
#pragma unroll
            for (int half = 0; half < 2; half++) {
                const int row = row0 + half*8;
                float v0 = c[mt][nt][half*2+0] + b0;
                float v1 = c[mt][nt][half*2+1] + b1;
                if (MODE == 2) {
                    v0 = gelu_tanh(v0); v1 = gelu_tanh(v1);
                } else if (MODE == 3) {
                    const float2 r2 = *(const float2*)&g_y[(size_t)row*128 + o0 + colb];
                    v0 += (r2.x - m_s[o0+colb])   * r_s[o0+colb];
                    v1 += (r2.y - m_s[o0+colb+1]) * r_s[o0+colb+1];
                }
                // store
                if (MODE == 0) {
                    const int by = blockIdx.y;
                    float* base = (by < 2) ? g_q : (by < 4) ? g_k : g_v;
                    const int oc = (by & 1)*64 + colb;
                    *(float2*)&base[(size_t)(oc>>4)*(NTOK*HD) + (size_t)row*16 + (oc&15)]
                        = make_float2(v0, v1);
                } else if (MODE == 1) {
                    *(float2*)&g_y[(size_t)row*128 + o0 + colb] = make_float2(v0, v1);
                } else if (MODE == 2) {
                    *(float2*)&g_h1[(size_t)row*512 + o0 + colb] = make_float2(v0, v1);
                } else {
                    *(float2*)&g_u[(size_t)row*128 + o0 + colb] = make_float2(v0, v1);
                }
                if (MODE == 1 || MODE == 3) {
                    s[nt][0] += v0; s[nt][1] += v1;
                    q2[nt][0] += v0*v0; q2[nt][1] += v1*v1;
                }
            }
        }
    }

    if (MODE == 1 || MODE == 3) {
        // reduce over g (lanes tq, tq+4, ..., tq+28)
#pragma unroll
        for (int nt = 0; nt < 4; nt++) {
#pragma unroll
            for (int j = 0; j < 2; j++) {
                float a0 = s[nt][j], a1 = q2[nt][j];
#pragma unroll
                for (int off = 4; off < 32; off <<= 1) {
                    a0 += __shfl_xor_sync(0xffffffffu, a0, off);
                    a1 += __shfl_xor_sync(0xffffffffu, a1, off);
                }
                if (g == 0) {
                    const int idx = ((w*4 + nt)*4 + tq)*2 + j;
                    red[idx]       = a0;
                    red[256 + idx] = a1;
                }
            }
        }
        __syncthreads();
        if (tx < 64) {
            const int col = tx;
            const int wn2 = col >> 5;
            const int nt2 = (col >> 3) & 3;
            const int tq2 = (col & 7) >> 1;
            const int j2  = col & 1;
            float ssum = 0.f, ssq = 0.f;
#pragma unroll
            for (int wm2 = 0; wm2 < 4; wm2++) {
                const int idx = (((wm2*2 + wn2)*4 + nt2)*4 + tq2)*2 + j2;
                ssum += red[idx];
                ssq  += red[256 + idx];
            }
            g_part[blockIdx.x*256 + o0 + col]       = ssum;
            g_part[blockIdx.x*256 + 128 + o0 + col] = ssq;
        }
    }
}

// ---------------- attention: smem-staged, block = (z-column, head) ----------------
#define RS  17                // smem row stride (16 ch + 1 pad)
#define PSZ 548               // plane stride = 32*17 + 4 (conflict-free 27-lane reads)
__global__ __launch_bounds__(256) void attn_smem(const float* __restrict__ rpb) {
    __shared__ float Ks[9*PSZ];
    __shared__ float Vs[9*PSZ];
    __shared__ float Qs[32*16];
    __shared__ float rpbs[125];

    const int cw = blockIdx.x;           // hh*32+ww
    const int h  = blockIdx.y;
    const int hh = cw >> 5, ww = cw & 31;
    const int sh = min(max(hh-1, 0), 29);
    const int sw = min(max(ww-1, 0), 29);
    const int t = threadIdx.x;
    const size_t hb = (size_t)h * (NTOK*HD);

    // stage K,V: 9 columns x 32 z x 16 ch (each column contiguous 512 floats)
    for (int idx = t; idx < 1152; idx += 256) {
        const int col = idx >> 7;        // 0..8
        const int rem = idx & 127;       // float4 index within column
        const int a = col/3, b = col - a*3;
        const int nbase = ((sh+a)*32 + (sw+b))*32;
        const int z = rem >> 2, c4 = rem & 3;
        float4 kv = *(const float4*)&g_k[hb + (size_t)nbase*16 + rem*4];
        float4 vv = *(const float4*)&g_v[hb + (size_t)nbase*16 + rem*4];
        float* dk = &Ks[col*PSZ + z*RS + c4*4];
        float* dv = &Vs[col*PSZ + z*RS + c4*4];
        dk[0]=kv.x; dk[1]=kv.y; dk[2]=kv.z; dk[3]=kv.w;
        dv[0]=vv.x; dv[1]=vv.y; dv[2]=vv.z; dv[3]=vv.w;
    }
    if (t < 128) {
        const int z = t >> 2, c4 = t & 3;
        float4 qv = *(const float4*)&g_q[hb + (size_t)(cw*32 + z)*16 + c4*4];
        float* dq = &Qs[z*16 + c4*4];
        dq[0]=qv.x*0.25f; dq[1]=qv.y*0.25f; dq[2]=qv.z*0.25f; dq[3]=qv.w*0.25f;
    }
    if (t < 125) rpbs[t] = rpb[h*125 + t];
    __syncthreads();

    const int w = t >> 5, lane = t & 31;
    int a = 0, b = 0, jz = 0;
    if (lane < 27) { a = lane/9; b = (lane - a*9)/3; jz = lane - a*9 - b*3; }
    const int colp = a*3 + b;
    const int rh = sh + a - hh + 2;
    const int rw = sw + b - ww + 2;

#pragma unroll 1
    for (int tz = 0; tz < 4; tz++) {
        const int z  = w*4 + tz;
        const int sz = min(max(z-1, 0), 29);
        float sc = -1e30f;
        if (lane < 27) {
            const float* kr = &Ks[colp*PSZ + (sz+jz)*RS];
            const float* qr = &Qs[z*16];
            float sdot = 0.f;
#pragma unroll
            for (int cc = 0; cc < 16; cc++) sdot += qr[cc]*kr[cc];
            const int rz = sz + jz - z + 2;
            sc = sdot + rpbs[(rh*5 + rw)*5 + rz];
        }
        float mx = sc;
#pragma unroll
        for (int off = 16; off; off >>= 1) mx = fmaxf(mx, __shfl_xor_sync(0xffffffffu, mx, off));
        float p = (lane < 27) ? __expf(sc - mx) : 0.f;
        float su = p;
#pragma unroll
        for (int off = 16; off; off >>= 1) su += __shfl_xor_sync(0xffffffffu, su, off);
        const float inv = 1.f / su;

        float acc = 0.f;
#pragma unroll
        for (int j = 0; j < 27; j++) {
            const float pj = __shfl_sync(0xffffffffu, p, j);
            const int cj = (j/9)*3 + ((j%9)/3);   // compile-time
            const int zj = j % 3;                 // compile-time
            if (lane < 16) acc += pj * Vs[cj*PSZ + (sz+zj)*RS + lane];
        }
        if (lane < 16)
            g_attn[hb + (size_t)(cw*32 + z)*16 + lane] = acc * inv;
    }
}

// ---------------- final reduce: 256 partial blocks -> stats ----------------
__global__ __launch_bounds__(256) void reduce_final() {
    const int t = threadIdx.x;           // slot 0..255
    float s = 0.f;
#pragma unroll 8
    for (int bx = 0; bx < 256; bx++) s += g_part[bx*256 + t];
    g_stats[t] = s;
}

// ---------------- final instance-norm + transpose to [C][N] ----------------
__global__ __launch_bounds__(256) void norm_transpose(float* __restrict__ out) {
    __shared__ float tile[32][33];
    const int n0 = blockIdx.x*32, c0 = blockIdx.y*32;
    const int txx = threadIdx.x & 31, tyy = threadIdx.x >> 5;
    const int c = c0 + txx;
    float m   = g_stats[c]     * INVN;
    float var = g_stats[c+128] * INVN - m*m;
    float rs  = rsqrtf(var + EPSF);
#pragma unroll
    for (int r = 0; r < 32; r += 8)
        tile[tyy+r][txx] = (g_u[(size_t)(n0+tyy+r)*128 + c] - m) * rs;
    __syncthreads();
#pragma unroll
    for (int r = 0; r < 32; r += 8)
        out[(size_t)(c0+tyy+r)*NTOK + n0 + txx] = tile[txx][tyy+r];
}

// ---------------- launch ----------------
extern "C" void kernel_launch(void* const* d_in, const int* in_sizes, int n_in,
                              void* d_out, int out_size) {
    const float* x      = (const float*)d_in[0];
    const float* w_qkv  = (const float*)d_in[1];
    const float* b_qkv  = (const float*)d_in[2];
    const float* rpb    = (const float*)d_in[3];
    const float* w_proj = (const float*)d_in[4];
    const float* b_proj = (const float*)d_in[5];
    const float* w_ffn1 = (const float*)d_in[6];
    const float* b_ffn1 = (const float*)d_in[7];
    const float* w_ffn2 = (const float*)d_in[8];
    const float* b_ffn2 = (const float*)d_in[9];
    float* out = (float*)d_out;

    transpose_x<<<dim3(NTOK/32, CCH/32), 256>>>(x);
    mma_gemm<128,0><<<dim3(256, 6), 256>>>(w_qkv, b_qkv);
    attn_smem<<<dim3(1024, NHEADS), 256>>>(rpb);
    mma_gemm<128,1><<<dim3(256, 2), 256>>>(w_proj, b_proj);
    reduce_final<<<1, 256>>>();
    mma_gemm<128,2><<<dim3(256, 8), 256>>>(w_ffn1, b_ffn1);
    mma_gemm<512,3><<<dim3(256, 2), 256>>>(w_ffn2, b_ffn2);
    reduce_final<<<1, 256>>>();
    norm_transpose<<<dim3(NTOK/32, CCH/32), 256>>>(out);
}

// round 12
// speedup vs baseline: 2.7903x; 1.0767x over previous
#include <cuda_runtime.h>
#include <math.h>
#include <stdint.h>

#define NTOK 32768
#define CCH  128
#define CF   512
#define NHEADS 8
#define HD   16
#define EPSF 1e-5f
#define INVN (1.0f/32768.0f)

// ---------------- scratch (device globals) ----------------
__device__ uint32_t g_xt[NTOK*CCH];      // x^T as tf32 bits [n][128]
__device__ float    g_q[NHEADS*NTOK*HD]; // [h][n][16] f32
__device__ float    g_k[NHEADS*NTOK*HD];
__device__ float    g_v[NHEADS*NTOK*HD];
__device__ uint32_t g_attn[NTOK*CCH];    // attn out, tf32 bits [n][128]
__device__ float    g_y[NTOK*CCH];       // proj out f32 [n][128]
__device__ uint32_t g_t[NTOK*CCH];       // norm1(g_y) tf32 bits
__device__ uint32_t g_h1[NTOK*CF];       // gelu(ffn1) tf32 bits [n][512]
__device__ float    g_u[NTOK*CCH];       // ffn2 + residual f32
__device__ uint32_t g_wq[384*128];       // tf32 weights
__device__ uint32_t g_wp[128*128];
__device__ uint32_t g_w1[512*128];
__device__ uint32_t g_w2[128*512];
__device__ float    g_part[256*256];
__device__ float    g_stats[2*CCH];

__device__ __forceinline__ uint32_t f2tf32(float f) {
    uint32_t u; asm("cvt.rna.tf32.f32 %0, %1;" : "=r"(u) : "f"(f)); return u;
}
__device__ __forceinline__ float gelu_tanh(float x) {
    const float c0 = 0.7978845608028654f;
    float x3 = x*x*x;
    return 0.5f*x*(1.0f + tanhf(c0*(x + 0.044715f*x3)));
}
__device__ __forceinline__ void mma_tf32(float c[4], const uint32_t a[4], const uint32_t b[2]) {
    asm volatile(
        "mma.sync.aligned.m16n8k8.row.col.f32.tf32.tf32.f32 "
        "{%0,%1,%2,%3}, {%4,%5,%6,%7}, {%8,%9}, {%0,%1,%2,%3};"
        : "+f"(c[0]), "+f"(c[1]), "+f"(c[2]), "+f"(c[3])
        : "r"(a[0]), "r"(a[1]), "r"(a[2]), "r"(a[3]), "r"(b[0]), "r"(b[1]));
}
__device__ __forceinline__ uint32_t smem_u32(const void* p) {
    uint32_t a;
    asm("{ .reg .u64 t; cvta.to.shared.u64 t, %1; cvt.u32.u64 %0, t; }" : "=r"(a) : "l"(p));
    return a;
}
__device__ __forceinline__ void cp16(uint32_t s, const void* g) {
    asm volatile(
        "{\n\t.reg .u64 ga;\n\tcvta.to.global.u64 ga, %1;\n\t"
        "cp.async.cg.shared.global [%0], [ga], 16;\n\t}"
        :: "r"(s), "l"(g) : "memory");
}
#define CP_COMMIT()  asm volatile("cp.async.commit_group;" ::: "memory")
#define CP_WAIT(n)   asm volatile("cp.async.wait_group %0;" :: "n"(n) : "memory")

// ---------------- weight conversion f32 -> tf32 bits ----------------
// NOTE: dst selected IN DEVICE CODE. Passing a __device__ array symbol as a
// host-side kernel argument silently passes the host shadow address (the
// round-9/11 zero-output bug, unfaulting on GB300 because ATS makes host
// addresses writable).
__global__ __launch_bounds__(256) void cvt_w(const float* __restrict__ src,
                                             int which, int n) {
    uint32_t* dst = (which == 0) ? g_wq : (which == 1) ? g_wp
                  : (which == 2) ? g_w1 : g_w2;
    int i = blockIdx.x*256 + threadIdx.x;
    if (i < n) dst[i] = f2tf32(src[i]);
}

// ---------------- transpose x [C][N] -> g_xt tf32 [N][C] ----------------
__global__ __launch_bounds__(256) void transpose_x(const float* __restrict__ x) {
    __shared__ float tile[32][33];
    const int n0 = blockIdx.x*32, c0 = blockIdx.y*32;
    const int tx = threadIdx.x & 31, ty = threadIdx.x >> 5;
#pragma unroll
    for (int r = 0; r < 32; r += 8)
        tile[ty+r][tx] = x[(size_t)(c0+ty+r)*NTOK + n0 + tx];
    __syncthreads();
#pragma unroll
    for (int r = 0; r < 32; r += 8)
        g_xt[(size_t)(n0+ty+r)*CCH + c0 + tx] = f2tf32(tile[tx][ty+r]);
}

// ---------------- cp.async double-buffered tf32 GEMM (static smem only) ----
// out[n][o] = sum_k A[n][k] * W[o][k] (+bias, +epilogue)
// MODE 0: qkv  (A=g_xt,  B=g_wq, O=384 -> q/k/v f32 [h][n][16])
// MODE 1: proj (A=g_attn,B=g_wp, O=128 -> g_y f32; fused col partials)
// MODE 2: ffn1 (A=g_t,   B=g_w1, O=512 -> g_h1 tf32, gelu)
// MODE 3: ffn2 (A=g_h1,  B=g_w2, O=128 -> g_u = +bias + norm(g_y); fused partials)
// Block 128x64, K-chunk 16, 2-stage pipeline. Row stride 20 u32 (conflict-free).
#define A20 (128*20)
#define B20 (64*20)
#define STG (A20+B20)   // u32 per stage = 3840 (15360 B); x2 = 30720 B static

template<int KDIM, int MODE>
__global__ __launch_bounds__(256) void mma_gemm(const float* __restrict__ bias) {
    __shared__ uint32_t dsm[2*STG];
    __shared__ float red[512];
    __shared__ float m_s[128], r_s[128];

    const uint32_t* Ag = (MODE==0) ? g_xt : (MODE==1) ? g_attn : (MODE==2) ? g_t : g_h1;
    const uint32_t* Bg = (MODE==0) ? g_wq : (MODE==1) ? g_wp   : (MODE==2) ? g_w1 : g_w2;

    const int tx = threadIdx.x;
    const int w  = tx >> 5, lane = tx & 31;
    const int wm = w >> 1, wn = w & 1;
    const int g  = lane >> 2, tq = lane & 3;
    const int n0 = blockIdx.x * 128;
    const int o0 = blockIdx.y * 64;
    const uint32_t sbase = smem_u32(dsm);
    const int rr = tx >> 2, k4 = tx & 3;    // 64 row-groups x 4 quads
    const int NCH = KDIM / 16;

    if (MODE == 3 && tx < 128) {
        float m = g_stats[tx] * INVN;
        float var = g_stats[128+tx] * INVN - m*m;
        m_s[tx] = m;
        r_s[tx] = rsqrtf(var + EPSF);
    }

    // stage chunk kb (16 wide) into buffer s
    auto stage = [&](int s, int kb) {
        const uint32_t sa = sbase + (uint32_t)s*STG*4;
        const uint32_t sb = sa + A20*4;
#pragma unroll
        for (int i = 0; i < 2; i++) {
            const int n = i*64 + rr;
            cp16(sa + (uint32_t)(n*20 + k4*4)*4, Ag + (size_t)(n0+n)*KDIM + kb + k4*4);
        }
        cp16(sb + (uint32_t)(rr*20 + k4*4)*4, Bg + (size_t)(o0+rr)*KDIM + kb + k4*4);
        CP_COMMIT();
    };

    float c[2][4][4];
#pragma unroll
    for (int mt = 0; mt < 2; mt++)
#pragma unroll
        for (int nt = 0; nt < 4; nt++)
#pragma unroll
            for (int i = 0; i < 4; i++) c[mt][nt][i] = 0.f;

    stage(0, 0);
    stage(1, 16);

    for (int ch = 0; ch < NCH; ch++) {
        if (ch < NCH-1) CP_WAIT(1); else CP_WAIT(0);
        __syncthreads();
        const uint32_t* As = dsm + (ch & 1)*STG;
        const uint32_t* Bs = As + A20;
#pragma unroll
        for (int kt = 0; kt < 2; kt++) {
            const int kc = kt*8 + tq;
            uint32_t a[2][4], b[4][2];
#pragma unroll
            for (int mt = 0; mt < 2; mt++) {
                const int rb = (wm*32 + mt*16 + g)*20;
                a[mt][0] = As[rb + kc];
                a[mt][1] = As[rb + 8*20 + kc];
                a[mt][2] = As[rb + kc + 4];
                a[mt][3] = As[rb + 8*20 + kc + 4];
            }
#pragma unroll
            for (int nt = 0; nt < 4; nt++) {
                const int rb = ((wn*4+nt)*8 + g)*20;
                b[nt][0] = Bs[rb + kc];
                b[nt][1] = Bs[rb + kc + 4];
            }
#pragma unroll
            for (int mt = 0; mt < 2; mt++)
#pragma unroll
                for (int nt = 0; nt < 4; nt++)
                    mma_tf32(c[mt][nt], a[mt], b[nt]);
        }
        __syncthreads();
        if (ch + 2 < NCH) stage(ch & 1, (ch+2)*16);
    }

    // ---- epilogue ----
    float s[4][2], q2[4][2];
    if (MODE == 1 || MODE == 3) {
#pragma unroll
        for (int nt = 0; nt < 4; nt++) { s[nt][0]=s[nt][1]=q2[nt][0]=q2[nt][1]=0.f; }
    }

#pragma unroll
    for (int mt = 0; mt < 2; mt++) {
#pragma unroll
        for (int nt = 0; nt < 4; nt++) {
            const int colb = (wn*4 + nt)*8 + tq*2;
            const float b0 = bias[o0 + colb];
            const float b1 = bias[o0 + colb + 1];
            const int row0 = n0 + (wm*2 + mt)*16 + g;
#pragma unroll
            for (int half = 0; half < 2; half++) {
                const int row = row0 + half*8;
                float v0 = c[mt][nt][half*2+0] + b0;
                float v1 = c[mt][nt][half*2+1] + b1;
                if (MODE == 2) {
                    v0 = gelu_tanh(v0); v1 = gelu_tanh(v1);
                } else if (MODE == 3) {
                    const float2 r2 = *(const float2*)&g_y[(size_t)row*128 + o0 + colb];
                    v0 += (r2.x - m_s[o0+colb])   * r_s[o0+colb];
                    v1 += (r2.y - m_s[o0+colb+1]) * r_s[o0+colb+1];
                }
                if (MODE == 0) {
                    const int by = blockIdx.y;
                    float* base = (by < 2) ? g_q : (by < 4) ? g_k : g_v;
                    const int oc = (by & 1)*64 + colb;
                    *(float2*)&base[(size_t)(oc>>4)*(NTOK*HD) + (size_t)row*16 + (oc&15)]
                        = make_float2(v0, v1);
                } else if (MODE == 1) {
                    *(float2*)&g_y[(size_t)row*128 + o0 + colb] = make_float2(v0, v1);
                } else if (MODE == 2) {
                    *(uint2*)&g_h1[(size_t)row*512 + o0 + colb]
                        = make_uint2(f2tf32(v0), f2tf32(v1));
                } else {
                    *(float2*)&g_u[(size_t)row*128 + o0 + colb] = make_float2(v0, v1);
                }
                if (MODE == 1 || MODE == 3) {
                    s[nt][0] += v0; s[nt][1] += v1;
                    q2[nt][0] += v0*v0; q2[nt][1] += v1*v1;
                }
            }
        }
    }

    if (MODE == 1 || MODE == 3) {
#pragma unroll
        for (int nt = 0; nt < 4; nt++) {
#pragma unroll
            for (int j = 0; j < 2; j++) {
                float a0 = s[nt][j], a1 = q2[nt][j];
#pragma unroll
                for (int off = 4; off < 32; off <<= 1) {
                    a0 += __shfl_xor_sync(0xffffffffu, a0, off);
                    a1 += __shfl_xor_sync(0xffffffffu, a1, off);
                }
                if (g == 0) {
                    const int idx = ((w*4 + nt)*4 + tq)*2 + j;
                    red[idx]       = a0;
                    red[256 + idx] = a1;
                }
            }
        }
        __syncthreads();
        if (tx < 64) {
            const int col = tx;
            const int wn2 = col >> 5;
            const int nt2 = (col >> 3) & 3;
            const int tq2 = (col & 7) >> 1;
            const int j2  = col & 1;
            float ssum = 0.f, ssq = 0.f;
#pragma unroll
            for (int wm2 = 0; wm2 < 4; wm2++) {
                const int idx = (((wm2*2 + wn2)*4 + nt2)*4 + tq2)*2 + j2;
                ssum += red[idx];
                ssq  += red[256 + idx];
            }
            g_part[blockIdx.x*256 + o0 + col]       = ssum;
            g_part[blockIdx.x*256 + 128 + o0 + col] = ssq;
        }
    }
}

// ---------------- attention: smem-staged, block = (z-column, head) ----------------
#define RS  17
#define PSZ 548
__global__ __launch_bounds__(256) void attn_smem(const float* __restrict__ rpb) {
    __shared__ float Ks[9*PSZ];
    __shared__ float Vs[9*PSZ];
    __shared__ float Qs[32*16];
    __shared__ float rpbs[125];

    const int cw = blockIdx.x;
    const int h  = blockIdx.y;
    const int hh = cw >> 5, ww = cw & 31;
    const int sh = min(max(hh-1, 0), 29);
    const int sw = min(max(ww-1, 0), 29);
    const int t = threadIdx.x;
    const size_t hb = (size_t)h * (NTOK*HD);

    for (int idx = t; idx < 1152; idx += 256) {
        const int col = idx >> 7;
        const int rem = idx & 127;
        const int a = col/3, b = col - a*3;
        const int nbase = ((sh+a)*32 + (sw+b))*32;
        const int z = rem >> 2, c4 = rem & 3;
        float4 kv = *(const float4*)&g_k[hb + (size_t)nbase*16 + rem*4];
        float4 vv = *(const float4*)&g_v[hb + (size_t)nbase*16 + rem*4];
        float* dk = &Ks[col*PSZ + z*RS + c4*4];
        float* dv = &Vs[col*PSZ + z*RS + c4*4];
        dk[0]=kv.x; dk[1]=kv.y; dk[2]=kv.z; dk[3]=kv.w;
        dv[0]=vv.x; dv[1]=vv.y; dv[2]=vv.z; dv[3]=vv.w;
    }
    if (t < 128) {
        const int z = t >> 2, c4 = t & 3;
        float4 qv = *(const float4*)&g_q[hb + (size_t)(cw*32 + z)*16 + c4*4];
        float* dq = &Qs[z*16 + c4*4];
        dq[0]=qv.x*0.25f; dq[1]=qv.y*0.25f; dq[2]=qv.z*0.25f; dq[3]=qv.w*0.25f;
    }
    if (t < 125) rpbs[t] = rpb[h*125 + t];
    __syncthreads();

    const int w = t >> 5, lane = t & 31;
    int a = 0, b = 0, jz = 0;
    if (lane < 27) { a = lane/9; b = (lane - a*9)/3; jz = lane - a*9 - b*3; }
    const int colp = a*3 + b;
    const int rh = sh + a - hh + 2;
    const int rw = sw + b - ww + 2;

#pragma unroll 1
    for (int tz = 0; tz < 4; tz++) {
        const int z  = w*4 + tz;
        const int sz = min(max(z-1, 0), 29);
        float sc = -1e30f;
        if (lane < 27) {
            const float* kr = &Ks[colp*PSZ + (sz+jz)*RS];
            const float* qr = &Qs[z*16];
            float sdot = 0.f;
#pragma unroll
            for (int cc = 0; cc < 16; cc++) sdot += qr[cc]*kr[cc];
            const int rz = sz + jz - z + 2;
            sc = sdot + rpbs[(rh*5 + rw)*5 + rz];
        }
        float mx = sc;
#pragma unroll
        for (int off = 16; off; off >>= 1) mx = fmaxf(mx, __shfl_xor_sync(0xffffffffu, mx, off));
        float p = (lane < 27) ? __expf(sc - mx) : 0.f;
        float su = p;
#pragma unroll
        for (int off = 16; off; off >>= 1) su += __shfl_xor_sync(0xffffffffu, su, off);
        const float inv = 1.f / su;

        float acc = 0.f;
#pragma unroll
        for (int j = 0; j < 27; j++) {
            const float pj = __shfl_sync(0xffffffffu, p, j);
            const int cj = (j/9)*3 + ((j%9)/3);
            const int zj = j % 3;
            if (lane < 16) acc += pj * Vs[cj*PSZ + (sz+zj)*RS + lane];
        }
        if (lane < 16)
            g_attn[(size_t)(cw*32 + z)*128 + h*16 + lane] = f2tf32(acc * inv);
    }
}

// ---------------- final reduce: 256 partial blocks -> stats ----------------
__global__ __launch_bounds__(256) void reduce_final() {
    const int t = threadIdx.x;
    float s = 0.f;
#pragma unroll 8
    for (int bx = 0; bx < 256; bx++) s += g_part[bx*256 + t];
    g_stats[t] = s;
}

// ---------------- norm1 applied to g_y -> g_t (tf32 bits) ----------------
__global__ __launch_bounds__(256) void norm_tf32() {
    const int idx = blockIdx.x*256 + threadIdx.x;
    const int c = idx & 127;
    float m   = g_stats[c]     * INVN;
    float var = g_stats[c+128] * INVN - m*m;
    g_t[idx] = f2tf32((g_y[idx] - m) * rsqrtf(var + EPSF));
}

// ---------------- final instance-norm + transpose to [C][N] ----------------
__global__ __launch_bounds__(256) void norm_transpose(float* __restrict__ out) {
    __shared__ float tile[32][33];
    const int n0 = blockIdx.x*32, c0 = blockIdx.y*32;
    const int txx = threadIdx.x & 31, tyy = threadIdx.x >> 5;
    const int c = c0 + txx;
    float m   = g_stats[c]     * INVN;
    float var = g_stats[c+128] * INVN - m*m;
    float rs  = rsqrtf(var + EPSF);
#pragma unroll
    for (int r = 0; r < 32; r += 8)
        tile[tyy+r][txx] = (g_u[(size_t)(n0+tyy+r)*128 + c] - m) * rs;
    __syncthreads();
#pragma unroll
    for (int r = 0; r < 32; r += 8)
        out[(size_t)(c0+tyy+r)*NTOK + n0 + txx] = tile[txx][tyy+r];
}

// ---------------- launch ----------------
extern "C" void kernel_launch(void* const* d_in, const int* in_sizes, int n_in,
                              void* d_out, int out_size) {
    const float* x      = (const float*)d_in[0];
    const float* w_qkv  = (const float*)d_in[1];
    const float* b_qkv  = (const float*)d_in[2];
    const float* rpb    = (const float*)d_in[3];
    const float* w_proj = (const float*)d_in[4];
    const float* b_proj = (const float*)d_in[5];
    const float* w_ffn1 = (const float*)d_in[6];
    const float* b_ffn1 = (const float*)d_in[7];
    const float* w_ffn2 = (const float*)d_in[8];
    const float* b_ffn2 = (const float*)d_in[9];
    float* out = (float*)d_out;

    cvt_w<<<192, 256>>>(w_qkv,  0, 384*128);
    cvt_w<<<64,  256>>>(w_proj, 1, 128*128);
    cvt_w<<<256, 256>>>(w_ffn1, 2, 512*128);
    cvt_w<<<256, 256>>>(w_ffn2, 3, 128*512);
    transpose_x<<<dim3(NTOK/32, CCH/32), 256>>>(x);
    mma_gemm<128,0><<<dim3(256, 6), 256>>>(b_qkv);
    attn_smem<<<dim3(1024, NHEADS), 256>>>(rpb);
    mma_gemm<128,1><<<dim3(256, 2), 256>>>(b_proj);
    reduce_final<<<1, 256>>>();
    norm_tf32<<<NTOK*CCH/256, 256>>>();
    mma_gemm<128,2><<<dim3(256, 8), 256>>>(b_ffn1);
    mma_gemm<512,3><<<dim3(256, 2), 256>>>(b_ffn2);
    reduce_final<<<1, 256>>>();
    norm_transpose<<<dim3(NTOK/32, CCH/32), 256>>>(out);
}

// round 13
// speedup vs baseline: 2.8850x; 1.0339x over previous
#include <cuda_runtime.h>
#include <math.h>
#include <stdint.h>

#define NTOK 32768
#define CCH  128
#define CF   512
#define NHEADS 8
#define HD   16
#define EPSF 1e-5f
#define INVN (1.0f/32768.0f)

// ---------------- scratch (device globals) ----------------
__device__ uint32_t g_xt[NTOK*CCH];      // x^T as tf32 bits [n][128]
__device__ float    g_q[NHEADS*NTOK*HD]; // [h][n][16] f32
__device__ float    g_k[NHEADS*NTOK*HD];
__device__ float    g_v[NHEADS*NTOK*HD];
__device__ uint32_t g_attn[NTOK*CCH];    // attn out, tf32 bits [n][128]
__device__ float    g_y[NTOK*CCH];       // proj out f32 [n][128]
__device__ uint32_t g_t[NTOK*CCH];       // norm1(g_y) tf32 bits
__device__ uint32_t g_h1[NTOK*CF];       // gelu(ffn1) tf32 bits [n][512]
__device__ float    g_u[NTOK*CCH];       // ffn2 + residual f32
__device__ uint32_t g_wq[384*128];       // tf32 weights
__device__ uint32_t g_wp[128*128];
__device__ uint32_t g_w1[512*128];
__device__ uint32_t g_w2[128*512];
__device__ float    g_part[256*256];
__device__ float    g_stats[2*CCH];

__device__ __forceinline__ uint32_t f2tf32(float f) {
    uint32_t u; asm("cvt.rna.tf32.f32 %0, %1;" : "=r"(u) : "f"(f)); return u;
}
__device__ __forceinline__ float gelu_tanh(float x) {
    const float c0 = 0.7978845608028654f;
    float x3 = x*x*x;
    return 0.5f*x*(1.0f + tanhf(c0*(x + 0.044715f*x3)));
}
__device__ __forceinline__ void mma_tf32(float c[4], const uint32_t a[4], const uint32_t b[2]) {
    asm volatile(
        "mma.sync.aligned.m16n8k8.row.col.f32.tf32.tf32.f32 "
        "{%0,%1,%2,%3}, {%4,%5,%6,%7}, {%8,%9}, {%0,%1,%2,%3};"
        : "+f"(c[0]), "+f"(c[1]), "+f"(c[2]), "+f"(c[3])
        : "r"(a[0]), "r"(a[1]), "r"(a[2]), "r"(a[3]), "r"(b[0]), "r"(b[1]));
}
__device__ __forceinline__ uint32_t smem_u32(const void* p) {
    uint32_t a;
    asm("{ .reg .u64 t; cvta.to.shared.u64 t, %1; cvt.u32.u64 %0, t; }" : "=r"(a) : "l"(p));
    return a;
}
__device__ __forceinline__ void cp16(uint32_t s, const void* g) {
    asm volatile(
        "{\n\t.reg .u64 ga;\n\tcvta.to.global.u64 ga, %1;\n\t"
        "cp.async.cg.shared.global [%0], [ga], 16;\n\t}"
        :: "r"(s), "l"(g) : "memory");
}
#define CP_COMMIT()  asm volatile("cp.async.commit_group;" ::: "memory")
#define CP_WAIT(n)   asm volatile("cp.async.wait_group %0;" :: "n"(n) : "memory")

// ---------------- all-weights conversion f32 -> tf32 bits, ONE launch ------
// dst arrays selected in device code (host-side __device__ symbol decay passes
// the host shadow address — the round-9/11 zero-output bug).
__global__ __launch_bounds__(256) void cvt_all(const float* __restrict__ wq,
                                               const float* __restrict__ wp,
                                               const float* __restrict__ w1,
                                               const float* __restrict__ w2) {
    int i = blockIdx.x*256 + threadIdx.x;              // 0 .. 196607
    if (i < 49152)        g_wq[i]          = f2tf32(wq[i]);
    else if (i < 65536)   g_wp[i - 49152]  = f2tf32(wp[i - 49152]);
    else if (i < 131072)  g_w1[i - 65536]  = f2tf32(w1[i - 65536]);
    else                  g_w2[i - 131072] = f2tf32(w2[i - 131072]);
}

// ---------------- transpose x [C][N] -> g_xt tf32 [N][C] ----------------
__global__ __launch_bounds__(256) void transpose_x(const float* __restrict__ x) {
    __shared__ float tile[32][33];
    const int n0 = blockIdx.x*32, c0 = blockIdx.y*32;
    const int tx = threadIdx.x & 31, ty = threadIdx.x >> 5;
#pragma unroll
    for (int r = 0; r < 32; r += 8)
        tile[ty+r][tx] = x[(size_t)(c0+ty+r)*NTOK + n0 + tx];
    __syncthreads();
#pragma unroll
    for (int r = 0; r < 32; r += 8)
        g_xt[(size_t)(n0+ty+r)*CCH + c0 + tx] = f2tf32(tile[tx][ty+r]);
}

// ---------------- cp.async double-buffered tf32 GEMM, 128x128 tile --------
// out[n][o] = sum_k A[n][k] * W[o][k] (+bias, +epilogue)
// MODE 0: qkv  (A=g_xt,  B=g_wq, O=384 -> by picks q/k/v, [h][n][16] f32)
// MODE 1: proj (A=g_attn,B=g_wp, O=128 -> g_y f32; fused col partials)
// MODE 2: ffn1 (A=g_t,   B=g_w1, O=512 -> g_h1 tf32, gelu)
// MODE 3: ffn2 (A=g_h1,  B=g_w2, O=128 -> g_u = +bias + norm(g_y); fused partials)
// 8 warps (wm 0..3, wn 0..1), warp tile 32x128? no: 32(M) x 64(N) -> 2 mt x 8 nt.
// K-chunk 16, 2-stage pipeline, row stride 20 u32 (conflict-free).
#define AR20 (128*20)
#define STG2 (2*AR20)      // A + B per stage = 5120 u32 (20 KB); x2 = 40 KB

template<int KDIM, int MODE>
__global__ __launch_bounds__(256) void mma_gemm(const float* __restrict__ bias) {
    __shared__ uint32_t dsm[2*STG2];
    __shared__ float red[1024];
    __shared__ float m_s[128], r_s[128];

    const uint32_t* Ag = (MODE==0) ? g_xt : (MODE==1) ? g_attn : (MODE==2) ? g_t : g_h1;
    const uint32_t* Bg = (MODE==0) ? g_wq : (MODE==1) ? g_wp   : (MODE==2) ? g_w1 : g_w2;

    const int tx = threadIdx.x;
    const int w  = tx >> 5, lane = tx & 31;
    const int wm = w >> 1, wn = w & 1;
    const int g  = lane >> 2, tq = lane & 3;
    const int n0 = blockIdx.x * 128;
    const int o0 = blockIdx.y * 128;
    const uint32_t sbase = smem_u32(dsm);
    const int rr = tx >> 2, k4 = tx & 3;    // 64 row-groups x 4 quads
    const int NCH = KDIM / 16;

    if (MODE == 3 && tx < 128) {
        float m = g_stats[tx] * INVN;
        float var = g_stats[128+tx] * INVN - m*m;
        m_s[tx] = m;
        r_s[tx] = rsqrtf(var + EPSF);
    }

    // stage chunk kb (16 wide): A rows 0..127 and B rows 0..127
    auto stage = [&](int s, int kb) {
        const uint32_t sa = sbase + (uint32_t)s*STG2*4;
        const uint32_t sb = sa + AR20*4;
#pragma unroll
        for (int i = 0; i < 2; i++) {
            const int n = i*64 + rr;
            cp16(sa + (uint32_t)(n*20 + k4*4)*4, Ag + (size_t)(n0+n)*KDIM + kb + k4*4);
            cp16(sb + (uint32_t)(n*20 + k4*4)*4, Bg + (size_t)(o0+n)*KDIM + kb + k4*4);
        }
        CP_COMMIT();
    };

    float c[2][8][4];
#pragma unroll
    for (int mt = 0; mt < 2; mt++)
#pragma unroll
        for (int nt = 0; nt < 8; nt++)
#pragma unroll
            for (int i = 0; i < 4; i++) c[mt][nt][i] = 0.f;

    stage(0, 0);
    stage(1, 16);

    for (int ch = 0; ch < NCH; ch++) {
        if (ch < NCH-1) CP_WAIT(1); else CP_WAIT(0);
        __syncthreads();
        const uint32_t* As = dsm + (ch & 1)*STG2;
        const uint32_t* Bs = As + AR20;
#pragma unroll
        for (int kt = 0; kt < 2; kt++) {
            const int kc = kt*8 + tq;
            uint32_t a[2][4], b[8][2];
#pragma unroll
            for (int mt = 0; mt < 2; mt++) {
                const int rb = (wm*32 + mt*16 + g)*20;
                a[mt][0] = As[rb + kc];
                a[mt][1] = As[rb + 8*20 + kc];
                a[mt][2] = As[rb + kc + 4];
                a[mt][3] = As[rb + 8*20 + kc + 4];
            }
#pragma unroll
            for (int nt = 0; nt < 8; nt++) {
                const int rb = (wn*64 + nt*8 + g)*20;
                b[nt][0] = Bs[rb + kc];
                b[nt][1] = Bs[rb + kc + 4];
            }
#pragma unroll
            for (int mt = 0; mt < 2; mt++)
#pragma unroll
                for (int nt = 0; nt < 8; nt++)
                    mma_tf32(c[mt][nt], a[mt], b[nt]);
        }
        __syncthreads();
        if (ch + 2 < NCH) stage(ch & 1, (ch+2)*16);
    }

    // ---- epilogue ----
    float s[8][2], q2[8][2];
    if (MODE == 1 || MODE == 3) {
#pragma unroll
        for (int nt = 0; nt < 8; nt++) { s[nt][0]=s[nt][1]=q2[nt][0]=q2[nt][1]=0.f; }
    }

#pragma unroll
    for (int mt = 0; mt < 2; mt++) {
#pragma unroll
        for (int nt = 0; nt < 8; nt++) {
            const int colb = (wn*8 + nt)*8 + tq*2;       // 0..126 within 128
            const float b0 = bias[o0 + colb];
            const float b1 = bias[o0 + colb + 1];
            const int row0 = n0 + (wm*2 + mt)*16 + g;
#pragma unroll
            for (int half = 0; half < 2; half++) {
                const int row = row0 + half*8;
                float v0 = c[mt][nt][half*2+0] + b0;
                float v1 = c[mt][nt][half*2+1] + b1;
                if (MODE == 2) {
                    v0 = gelu_tanh(v0); v1 = gelu_tanh(v1);
                } else if (MODE == 3) {
                    const float2 r2 = *(const float2*)&g_y[(size_t)row*128 + colb];
                    v0 += (r2.x - m_s[colb])   * r_s[colb];
                    v1 += (r2.y - m_s[colb+1]) * r_s[colb+1];
                }
                if (MODE == 0) {
                    const int by = blockIdx.y;           // 0:q 1:k 2:v
                    float* base = (by == 0) ? g_q : (by == 1) ? g_k : g_v;
                    *(float2*)&base[(size_t)(colb>>4)*(NTOK*HD) + (size_t)row*16 + (colb&15)]
                        = make_float2(v0, v1);
                } else if (MODE == 1) {
                    *(float2*)&g_y[(size_t)row*128 + colb] = make_float2(v0, v1);
                } else if (MODE == 2) {
                    *(uint2*)&g_h1[(size_t)row*512 + o0 + colb]
                        = make_uint2(f2tf32(v0), f2tf32(v1));
                } else {
                    *(float2*)&g_u[(size_t)row*128 + colb] = make_float2(v0, v1);
                }
                if (MODE == 1 || MODE == 3) {
                    s[nt][0] += v0; s[nt][1] += v1;
                    q2[nt][0] += v0*v0; q2[nt][1] += v1*v1;
                }
            }
        }
    }

    if (MODE == 1 || MODE == 3) {
        // reduce over g within warp; lanes g==0 (tq 0..3) hold column partials
#pragma unroll
        for (int nt = 0; nt < 8; nt++) {
#pragma unroll
            for (int j = 0; j < 2; j++) {
                float a0 = s[nt][j], a1 = q2[nt][j];
#pragma unroll
                for (int off = 4; off < 32; off <<= 1) {
                    a0 += __shfl_xor_sync(0xffffffffu, a0, off);
                    a1 += __shfl_xor_sync(0xffffffffu, a1, off);
                }
                if (g == 0) {
                    const int col = (wn*8 + nt)*8 + tq*2 + j;   // 0..127
                    red[col*4 + wm]       = a0;
                    red[512 + col*4 + wm] = a1;
                }
            }
        }
        __syncthreads();
        if (tx < 128) {
            const int col = tx;
            float ssum = 0.f, ssq = 0.f;
#pragma unroll
            for (int wm2 = 0; wm2 < 4; wm2++) {
                ssum += red[col*4 + wm2];
                ssq  += red[512 + col*4 + wm2];
            }
            g_part[blockIdx.x*256 + col]       = ssum;
            g_part[blockIdx.x*256 + 128 + col] = ssq;
        }
    }
}

// ---------------- attention: smem-staged, block = (z-column, head) ----------------
#define RS  17
#define PSZ 548
__global__ __launch_bounds__(256) void attn_smem(const float* __restrict__ rpb) {
    __shared__ float Ks[9*PSZ];
    __shared__ float Vs[9*PSZ];
    __shared__ float Qs[32*16];
    __shared__ float rpbs[125];

    const int cw = blockIdx.x;
    const int h  = blockIdx.y;
    const int hh = cw >> 5, ww = cw & 31;
    const int sh = min(max(hh-1, 0), 29);
    const int sw = min(max(ww-1, 0), 29);
    const int t = threadIdx.x;
    const size_t hb = (size_t)h * (NTOK*HD);

    for (int idx = t; idx < 1152; idx += 256) {
        const int col = idx >> 7;
        const int rem = idx & 127;
        const int a = col/3, b = col - a*3;
        const int nbase = ((sh+a)*32 + (sw+b))*32;
        const int z = rem >> 2, c4 = rem & 3;
        float4 kv = *(const float4*)&g_k[hb + (size_t)nbase*16 + rem*4];
        float4 vv = *(const float4*)&g_v[hb + (size_t)nbase*16 + rem*4];
        float* dk = &Ks[col*PSZ + z*RS + c4*4];
        float* dv = &Vs[col*PSZ + z*RS + c4*4];
        dk[0]=kv.x; dk[1]=kv.y; dk[2]=kv.z; dk[3]=kv.w;
        dv[0]=vv.x; dv[1]=vv.y; dv[2]=vv.z; dv[3]=vv.w;
    }
    if (t < 128) {
        const int z = t >> 2, c4 = t & 3;
        float4 qv = *(const float4*)&g_q[hb + (size_t)(cw*32 + z)*16 + c4*4];
        float* dq = &Qs[z*16 + c4*4];
        dq[0]=qv.x*0.25f; dq[1]=qv.y*0.25f; dq[2]=qv.z*0.25f; dq[3]=qv.w*0.25f;
    }
    if (t < 125) rpbs[t] = rpb[h*125 + t];
    __syncthreads();

    const int w = t >> 5, lane = t & 31;
    int a = 0, b = 0, jz = 0;
    if (lane < 27) { a = lane/9; b = (lane - a*9)/3; jz = lane - a*9 - b*3; }
    const int colp = a*3 + b;
    const int rh = sh + a - hh + 2;
    const int rw = sw + b - ww + 2;

#pragma unroll 1
    for (int tz = 0; tz < 4; tz++) {
        const int z  = w*4 + tz;
        const int sz = min(max(z-1, 0), 29);
        float sc = -1e30f;
        if (lane < 27) {
            const float* kr = &Ks[colp*PSZ + (sz+jz)*RS];
            const float* qr = &Qs[z*16];
            float sdot = 0.f;
#pragma unroll
            for (int cc = 0; cc < 16; cc++) sdot += qr[cc]*kr[cc];
            const int rz = sz + jz - z + 2;
            sc = sdot + rpbs[(rh*5 + rw)*5 + rz];
        }
        float mx = sc;
#pragma unroll
        for (int off = 16; off; off >>= 1) mx = fmaxf(mx, __shfl_xor_sync(0xffffffffu, mx, off));
        float p = (lane < 27) ? __expf(sc - mx) : 0.f;
        float su = p;
#pragma unroll
        for (int off = 16; off; off >>= 1) su += __shfl_xor_sync(0xffffffffu, su, off);
        const float inv = 1.f / su;

        float acc = 0.f;
#pragma unroll
        for (int j = 0; j < 27; j++) {
            const float pj = __shfl_sync(0xffffffffu, p, j);
            const int cj = (j/9)*3 + ((j%9)/3);
            const int zj = j % 3;
            if (lane < 16) acc += pj * Vs[cj*PSZ + (sz+zj)*RS + lane];
        }
        if (lane < 16)
            g_attn[(size_t)(cw*32 + z)*128 + h*16 + lane] = f2tf32(acc * inv);
    }
}

// ---------------- final reduce: 256 partial blocks -> stats ----------------
__global__ __launch_bounds__(256) void reduce_final() {
    const int t = threadIdx.x;
    float s = 0.f;
#pragma unroll 8
    for (int bx = 0; bx < 256; bx++) s += g_part[bx*256 + t];
    g_stats[t] = s;
}

// ---------------- norm1 applied to g_y -> g_t (tf32 bits) ----------------
__global__ __launch_bounds__(256) void norm_tf32() {
    const int idx = blockIdx.x*256 + threadIdx.x;
    const int c = idx & 127;
    float m   = g_stats[c]     * INVN;
    float var = g_stats[c+128] * INVN - m*m;
    g_t[idx] = f2tf32((g_y[idx] - m) * rsqrtf(var + EPSF));
}

// ---------------- final instance-norm + transpose to [C][N] ----------------
__global__ __launch_bounds__(256) void norm_transpose(float* __restrict__ out) {
    __shared__ float tile[32][33];
    const int n0 = blockIdx.x*32, c0 = blockIdx.y*32;
    const int txx = threadIdx.x & 31, tyy = threadIdx.x >> 5;
    const int c = c0 + txx;
    float m   = g_stats[c]     * INVN;
    float var = g_stats[c+128] * INVN - m*m;
    float rs  = rsqrtf(var + EPSF);
#pragma unroll
    for (int r = 0; r < 32; r += 8)
        tile[tyy+r][txx] = (g_u[(size_t)(n0+tyy+r)*128 + c] - m) * rs;
    __syncthreads();
#pragma unroll
    for (int r = 0; r < 32; r += 8)
        out[(size_t)(c0+tyy+r)*NTOK + n0 + txx] = tile[txx][tyy+r];
}

// ---------------- launch ----------------
extern "C" void kernel_launch(void* const* d_in, const int* in_sizes, int n_in,
                              void* d_out, int out_size) {
    const float* x      = (const float*)d_in[0];
    const float* w_qkv  = (const float*)d_in[1];
    const float* b_qkv  = (const float*)d_in[2];
    const float* rpb    = (const float*)d_in[3];
    const float* w_proj = (const float*)d_in[4];
    const float* b_proj = (const float*)d_in[5];
    const float* w_ffn1 = (const float*)d_in[6];
    const float* b_ffn1 = (const float*)d_in[7];
    const float* w_ffn2 = (const float*)d_in[8];
    const float* b_ffn2 = (const float*)d_in[9];
    float* out = (float*)d_out;

    cvt_all<<<768, 256>>>(w_qkv, w_proj, w_ffn1, w_ffn2);
    transpose_x<<<dim3(NTOK/32, CCH/32), 256>>>(x);
    mma_gemm<128,0><<<dim3(256, 3), 256>>>(b_qkv);
    attn_smem<<<dim3(1024, NHEADS), 256>>>(rpb);
    mma_gemm<128,1><<<dim3(256, 1), 256>>>(b_proj);
    reduce_final<<<1, 256>>>();
    norm_tf32<<<NTOK*CCH/256, 256>>>();
    mma_gemm<128,2><<<dim3(256, 4), 256>>>(b_ffn1);
    mma_gemm<512,3><<<dim3(256, 1), 256>>>(b_ffn2);
    reduce_final<<<1, 256>>>();
    norm_transpose<<<dim3(NTOK/32, CCH/32), 256>>>(out);
}

// round 14
// speedup vs baseline: 3.2643x; 1.1314x over previous
#include <cuda_runtime.h>
#include <math.h>
#include <stdint.h>

#define NTOK 32768
#define CCH  128
#define CF   512
#define NHEADS 8
#define HD   16
#define EPSF 1e-5f
#define INVN (1.0f/32768.0f)

// ---------------- scratch (device globals) ----------------
__device__ uint32_t g_xt[NTOK*CCH];      // x^T as tf32 bits [n][128]
__device__ float    g_q[NHEADS*NTOK*HD]; // [h][n][16] f32
__device__ float    g_k[NHEADS*NTOK*HD];
__device__ float    g_v[NHEADS*NTOK*HD];
__device__ uint32_t g_attn[NTOK*CCH];    // attn out, tf32 bits [n][128]
__device__ float    g_y[NTOK*CCH];       // proj out f32 [n][128]
__device__ uint32_t g_t[NTOK*CCH];       // norm1(g_y) tf32 bits
__device__ uint32_t g_h1[NTOK*CF];       // gelu(ffn1) tf32 bits [n][512]
__device__ float    g_u[NTOK*CCH];       // ffn2 + residual f32
__device__ uint32_t g_wq[384*128];       // tf32 weights
__device__ uint32_t g_wp[128*128];
__device__ uint32_t g_w1[512*128];
__device__ uint32_t g_w2[128*512];
__device__ float    g_part[256*256];
__device__ float    g_stats[2*CCH];

__device__ __forceinline__ uint32_t f2tf32(float f) {
    uint32_t u; asm("cvt.rna.tf32.f32 %0, %1;" : "=r"(u) : "f"(f)); return u;
}
__device__ __forceinline__ float gelu_tanh(float x) {
    const float c0 = 0.7978845608028654f;
    float x3 = x*x*x;
    return 0.5f*x*(1.0f + tanhf(c0*(x + 0.044715f*x3)));
}
__device__ __forceinline__ void mma_tf32(float c[4], const uint32_t a[4], const uint32_t b[2]) {
    asm volatile(
        "mma.sync.aligned.m16n8k8.row.col.f32.tf32.tf32.f32 "
        "{%0,%1,%2,%3}, {%4,%5,%6,%7}, {%8,%9}, {%0,%1,%2,%3};"
        : "+f"(c[0]), "+f"(c[1]), "+f"(c[2]), "+f"(c[3])
        : "r"(a[0]), "r"(a[1]), "r"(a[2]), "r"(a[3]), "r"(b[0]), "r"(b[1]));
}
__device__ __forceinline__ uint32_t smem_u32(const void* p) {
    uint32_t a;
    asm("{ .reg .u64 t; cvta.to.shared.u64 t, %1; cvt.u32.u64 %0, t; }" : "=r"(a) : "l"(p));
    return a;
}
__device__ __forceinline__ void cp16(uint32_t s, const void* g) {
    asm volatile(
        "{\n\t.reg .u64 ga;\n\tcvta.to.global.u64 ga, %1;\n\t"
        "cp.async.cg.shared.global [%0], [ga], 16;\n\t}"
        :: "r"(s), "l"(g) : "memory");
}
#define CP_COMMIT()  asm volatile("cp.async.commit_group;" ::: "memory")
#define CP_WAIT(n)   asm volatile("cp.async.wait_group %0;" :: "n"(n) : "memory")

// ---------------- all-weights conversion f32 -> tf32 bits, ONE launch ------
// dst arrays selected in device code (host-side __device__ symbol decay passes
// the host shadow address — the round-9/11 zero-output bug).
__global__ __launch_bounds__(256) void cvt_all(const float* __restrict__ wq,
                                               const float* __restrict__ wp,
                                               const float* __restrict__ w1,
                                               const float* __restrict__ w2) {
    int i = blockIdx.x*256 + threadIdx.x;              // 0 .. 196607
    if (i < 49152)        g_wq[i]          = f2tf32(wq[i]);
    else if (i < 65536)   g_wp[i - 49152]  = f2tf32(wp[i - 49152]);
    else if (i < 131072)  g_w1[i - 65536]  = f2tf32(w1[i - 65536]);
    else                  g_w2[i - 131072] = f2tf32(w2[i - 131072]);
}

// ---------------- transpose x [C][N] -> g_xt tf32 [N][C] ----------------
__global__ __launch_bounds__(256) void transpose_x(const float* __restrict__ x) {
    __shared__ float tile[32][33];
    const int n0 = blockIdx.x*32, c0 = blockIdx.y*32;
    const int tx = threadIdx.x & 31, ty = threadIdx.x >> 5;
#pragma unroll
    for (int r = 0; r < 32; r += 8)
        tile[ty+r][tx] = x[(size_t)(c0+ty+r)*NTOK + n0 + tx];
    __syncthreads();
#pragma unroll
    for (int r = 0; r < 32; r += 8)
        g_xt[(size_t)(n0+ty+r)*CCH + c0 + tx] = f2tf32(tile[tx][ty+r]);
}

// ---------------- cp.async double-buffered tf32 GEMM, 128x128 tile --------
#define AR20 (128*20)
#define STG2 (2*AR20)      // A + B per stage = 5120 u32 (20 KB); x2 = 40 KB

template<int KDIM, int MODE>
__global__ __launch_bounds__(256) void mma_gemm(const float* __restrict__ bias) {
    __shared__ uint32_t dsm[2*STG2];
    __shared__ float red[1024];
    __shared__ float m_s[128], r_s[128];

    const uint32_t* Ag = (MODE==0) ? g_xt : (MODE==1) ? g_attn : (MODE==2) ? g_t : g_h1;
    const uint32_t* Bg = (MODE==0) ? g_wq : (MODE==1) ? g_wp   : (MODE==2) ? g_w1 : g_w2;

    const int tx = threadIdx.x;
    const int w  = tx >> 5, lane = tx & 31;
    const int wm = w >> 1, wn = w & 1;
    const int g  = lane >> 2, tq = lane & 3;
    const int n0 = blockIdx.x * 128;
    const int o0 = blockIdx.y * 128;
    const uint32_t sbase = smem_u32(dsm);
    const int rr = tx >> 2, k4 = tx & 3;
    const int NCH = KDIM / 16;

    if (MODE == 3 && tx < 128) {
        float m = g_stats[tx] * INVN;
        float var = g_stats[128+tx] * INVN - m*m;
        m_s[tx] = m;
        r_s[tx] = rsqrtf(var + EPSF);
    }

    auto stage = [&](int s, int kb) {
        const uint32_t sa = sbase + (uint32_t)s*STG2*4;
        const uint32_t sb = sa + AR20*4;
#pragma unroll
        for (int i = 0; i < 2; i++) {
            const int n = i*64 + rr;
            cp16(sa + (uint32_t)(n*20 + k4*4)*4, Ag + (size_t)(n0+n)*KDIM + kb + k4*4);
            cp16(sb + (uint32_t)(n*20 + k4*4)*4, Bg + (size_t)(o0+n)*KDIM + kb + k4*4);
        }
        CP_COMMIT();
    };

    float c[2][8][4];
#pragma unroll
    for (int mt = 0; mt < 2; mt++)
#pragma unroll
        for (int nt = 0; nt < 8; nt++)
#pragma unroll
            for (int i = 0; i < 4; i++) c[mt][nt][i] = 0.f;

    stage(0, 0);
    stage(1, 16);

    for (int ch = 0; ch < NCH; ch++) {
        if (ch < NCH-1) CP_WAIT(1); else CP_WAIT(0);
        __syncthreads();
        const uint32_t* As = dsm + (ch & 1)*STG2;
        const uint32_t* Bs = As + AR20;
#pragma unroll
        for (int kt = 0; kt < 2; kt++) {
            const int kc = kt*8 + tq;
            uint32_t a[2][4], b[8][2];
#pragma unroll
            for (int mt = 0; mt < 2; mt++) {
                const int rb = (wm*32 + mt*16 + g)*20;
                a[mt][0] = As[rb + kc];
                a[mt][1] = As[rb + 8*20 + kc];
                a[mt][2] = As[rb + kc + 4];
                a[mt][3] = As[rb + 8*20 + kc + 4];
            }
#pragma unroll
            for (int nt = 0; nt < 8; nt++) {
                const int rb = (wn*64 + nt*8 + g)*20;
                b[nt][0] = Bs[rb + kc];
                b[nt][1] = Bs[rb + kc + 4];
            }
#pragma unroll
            for (int mt = 0; mt < 2; mt++)
#pragma unroll
                for (int nt = 0; nt < 8; nt++)
                    mma_tf32(c[mt][nt], a[mt], b[nt]);
        }
        __syncthreads();
        if (ch + 2 < NCH) stage(ch & 1, (ch+2)*16);
    }

    // ---- epilogue ----
    float s[8][2], q2[8][2];
    if (MODE == 1 || MODE == 3) {
#pragma unroll
        for (int nt = 0; nt < 8; nt++) { s[nt][0]=s[nt][1]=q2[nt][0]=q2[nt][1]=0.f; }
    }

#pragma unroll
    for (int mt = 0; mt < 2; mt++) {
#pragma unroll
        for (int nt = 0; nt < 8; nt++) {
            const int colb = (wn*8 + nt)*8 + tq*2;
            const float b0 = bias[o0 + colb];
            const float b1 = bias[o0 + colb + 1];
            const int row0 = n0 + (wm*2 + mt)*16 + g;
#pragma unroll
            for (int half = 0; half < 2; half++) {
                const int row = row0 + half*8;
                float v0 = c[mt][nt][half*2+0] + b0;
                float v1 = c[mt][nt][half*2+1] + b1;
                if (MODE == 2) {
                    v0 = gelu_tanh(v0); v1 = gelu_tanh(v1);
                } else if (MODE == 3) {
                    const float2 r2 = *(const float2*)&g_y[(size_t)row*128 + colb];
                    v0 += (r2.x - m_s[colb])   * r_s[colb];
                    v1 += (r2.y - m_s[colb+1]) * r_s[colb+1];
                }
                if (MODE == 0) {
                    const int by = blockIdx.y;
                    float* base = (by == 0) ? g_q : (by == 1) ? g_k : g_v;
                    *(float2*)&base[(size_t)(colb>>4)*(NTOK*HD) + (size_t)row*16 + (colb&15)]
                        = make_float2(v0, v1);
                } else if (MODE == 1) {
                    *(float2*)&g_y[(size_t)row*128 + colb] = make_float2(v0, v1);
                } else if (MODE == 2) {
                    *(uint2*)&g_h1[(size_t)row*512 + o0 + colb]
                        = make_uint2(f2tf32(v0), f2tf32(v1));
                } else {
                    *(float2*)&g_u[(size_t)row*128 + colb] = make_float2(v0, v1);
                }
                if (MODE == 1 || MODE == 3) {
                    s[nt][0] += v0; s[nt][1] += v1;
                    q2[nt][0] += v0*v0; q2[nt][1] += v1*v1;
                }
            }
        }
    }

    if (MODE == 1 || MODE == 3) {
#pragma unroll
        for (int nt = 0; nt < 8; nt++) {
#pragma unroll
            for (int j = 0; j < 2; j++) {
                float a0 = s[nt][j], a1 = q2[nt][j];
#pragma unroll
                for (int off = 4; off < 32; off <<= 1) {
                    a0 += __shfl_xor_sync(0xffffffffu, a0, off);
                    a1 += __shfl_xor_sync(0xffffffffu, a1, off);
                }
                if (g == 0) {
                    const int col = (wn*8 + nt)*8 + tq*2 + j;
                    red[col*4 + wm]       = a0;
                    red[512 + col*4 + wm] = a1;
                }
            }
        }
        __syncthreads();
        if (tx < 128) {
            const int col = tx;
            float ssum = 0.f, ssq = 0.f;
#pragma unroll
            for (int wm2 = 0; wm2 < 4; wm2++) {
                ssum += red[col*4 + wm2];
                ssq  += red[512 + col*4 + wm2];
            }
            g_part[blockIdx.x*256 + col]       = ssum;
            g_part[blockIdx.x*256 + 128 + col] = ssq;
        }
    }
}

// ---------------- attention: smem-staged, split score/AV phases -----------
// K tile: row stride 17, plane 548 (scalar score reads, verified layout).
// V tile: row stride 16, plane 524 (float4 staging stores, LDS.64 phase-B
//         reads conflict-free: each 16-lane phase covers 2 adjacent rows
//         whose bank halves are disjoint).
#define RSK  17
#define PSK  548
#define RSV  16
#define PSV  524
__global__ __launch_bounds__(256) void attn_smem(const float* __restrict__ rpb) {
    __shared__ float Ks[9*PSK];
    __shared__ float Vs[9*PSV];
    __shared__ float Qs[32*16];
    __shared__ float Ps[32*28];     // scaled probs per z
    __shared__ float rpbs[125];

    const int cw = blockIdx.x;
    const int h  = blockIdx.y;
    const int hh = cw >> 5, ww = cw & 31;
    const int sh = min(max(hh-1, 0), 29);
    const int sw = min(max(ww-1, 0), 29);
    const int t = threadIdx.x;
    const size_t hb = (size_t)h * (NTOK*HD);

    for (int idx = t; idx < 1152; idx += 256) {
        const int col = idx >> 7;
        const int rem = idx & 127;
        const int a = col/3, b = col - a*3;
        const int nbase = ((sh+a)*32 + (sw+b))*32;
        const int z = rem >> 2, c4 = rem & 3;
        float4 kv = *(const float4*)&g_k[hb + (size_t)nbase*16 + rem*4];
        float4 vv = *(const float4*)&g_v[hb + (size_t)nbase*16 + rem*4];
        float* dk = &Ks[col*PSK + z*RSK + c4*4];
        dk[0]=kv.x; dk[1]=kv.y; dk[2]=kv.z; dk[3]=kv.w;
        *(float4*)&Vs[col*PSV + z*RSV + c4*4] = vv;
    }
    if (t < 128) {
        const int z = t >> 2, c4 = t & 3;
        float4 qv = *(const float4*)&g_q[hb + (size_t)(cw*32 + z)*16 + c4*4];
        float* dq = &Qs[z*16 + c4*4];
        dq[0]=qv.x*0.25f; dq[1]=qv.y*0.25f; dq[2]=qv.z*0.25f; dq[3]=qv.w*0.25f;
    }
    if (t < 125) rpbs[t] = rpb[h*125 + t];
    __syncthreads();

    // ---- phase A: scores + softmax, store scaled probs ----
    const int w = t >> 5, lane = t & 31;
    int a = 0, b = 0, jz = 0;
    if (lane < 27) { a = lane/9; b = (lane - a*9)/3; jz = lane - a*9 - b*3; }
    const int colp = a*3 + b;
    const int rh = sh + a - hh + 2;
    const int rw = sw + b - ww + 2;

#pragma unroll 1
    for (int tz = 0; tz < 4; tz++) {
        const int z  = w*4 + tz;
        const int sz = min(max(z-1, 0), 29);
        float sc = -1e30f;
        if (lane < 27) {
            const float* kr = &Ks[colp*PSK + (sz+jz)*RSK];
            const float* qr = &Qs[z*16];
            float sdot = 0.f;
#pragma unroll
            for (int cc = 0; cc < 16; cc++) sdot += qr[cc]*kr[cc];
            const int rz = sz + jz - z + 2;
            sc = sdot + rpbs[(rh*5 + rw)*5 + rz];
        }
        float mx = sc;
#pragma unroll
        for (int off = 16; off; off >>= 1) mx = fmaxf(mx, __shfl_xor_sync(0xffffffffu, mx, off));
        float p = (lane < 27) ? __expf(sc - mx) : 0.f;
        float su = p;
#pragma unroll
        for (int off = 16; off; off >>= 1) su += __shfl_xor_sync(0xffffffffu, su, off);
        if (lane < 27) Ps[z*28 + lane] = p / su;
    }
    __syncthreads();

    // ---- phase B: AV, thread = (z, channel-pair) ----
    const int z2 = t >> 3;          // 0..31
    const int cp = t & 7;           // 0..7
    const int sz2 = min(max(z2-1, 0), 29);
    float ax = 0.f, ay = 0.f;
#pragma unroll
    for (int j = 0; j < 27; j++) {
        const int cj = j / 3;       // compile-time
        const int zj = j % 3;       // compile-time
        const float pj = Ps[z2*28 + j];
        const float2 v2 = *(const float2*)&Vs[cj*PSV + (sz2+zj)*RSV + cp*2];
        ax += pj * v2.x;
        ay += pj * v2.y;
    }
    *(uint2*)&g_attn[(size_t)(cw*32 + z2)*128 + h*16 + cp*2]
        = make_uint2(f2tf32(ax), f2tf32(ay));
}

// ---------------- final reduce: 256 partial blocks -> stats (1024 thr) ----
__global__ __launch_bounds__(1024) void reduce_final() {
    __shared__ float red[1024];
    const int t = threadIdx.x;
    const int slot = t & 255, part = t >> 8;   // 4 parts x 64 blocks
    float s = 0.f;
#pragma unroll 8
    for (int bx = part*64; bx < part*64 + 64; bx++) s += g_part[bx*256 + slot];
    red[part*256 + slot] = s;
    __syncthreads();
    if (t < 256) g_stats[t] = red[t] + red[256+t] + red[512+t] + red[768+t];
}

// ---------------- norm1 applied to g_y -> g_t (tf32 bits) ----------------
__global__ __launch_bounds__(256) void norm_tf32() {
    const int idx = blockIdx.x*256 + threadIdx.x;
    const int c = idx & 127;
    float m   = g_stats[c]     * INVN;
    float var = g_stats[c+128] * INVN - m*m;
    g_t[idx] = f2tf32((g_y[idx] - m) * rsqrtf(var + EPSF));
}

// ---------------- final instance-norm + transpose to [C][N] ----------------
__global__ __launch_bounds__(256) void norm_transpose(float* __restrict__ out) {
    __shared__ float tile[32][33];
    const int n0 = blockIdx.x*32, c0 = blockIdx.y*32;
    const int txx = threadIdx.x & 31, tyy = threadIdx.x >> 5;
    const int c = c0 + txx;
    float m   = g_stats[c]     * INVN;
    float var = g_stats[c+128] * INVN - m*m;
    float rs  = rsqrtf(var + EPSF);
#pragma unroll
    for (int r = 0; r < 32; r += 8)
        tile[tyy+r][txx] = (g_u[(size_t)(n0+tyy+r)*128 + c] - m) * rs;
    __syncthreads();
#pragma unroll
    for (int r = 0; r < 32; r += 8)
        out[(size_t)(c0+tyy+r)*NTOK + n0 + txx] = tile[txx][tyy+r];
}

// ---------------- launch ----------------
extern "C" void kernel_launch(void* const* d_in, const int* in_sizes, int n_in,
                              void* d_out, int out_size) {
    const float* x      = (const float*)d_in[0];
    const float* w_qkv  = (const float*)d_in[1];
    const float* b_qkv  = (const float*)d_in[2];
    const float* rpb    = (const float*)d_in[3];
    const float* w_proj = (const float*)d_in[4];
    const float* b_proj = (const float*)d_in[5];
    const float* w_ffn1 = (const float*)d_in[6];
    const float* b_ffn1 = (const float*)d_in[7];
    const float* w_ffn2 = (const float*)d_in[8];
    const float* b_ffn2 = (const float*)d_in[9];
    float* out = (float*)d_out;

    cvt_all<<<768, 256>>>(w_qkv, w_proj, w_ffn1, w_ffn2);
    transpose_x<<<dim3(NTOK/32, CCH/32), 256>>>(x);
    mma_gemm<128,0><<<dim3(256, 3), 256>>>(b_qkv);
    attn_smem<<<dim3(1024, NHEADS), 256>>>(rpb);
    mma_gemm<128,1><<<dim3(256, 1), 256>>>(b_proj);
    reduce_final<<<1, 1024>>>();
    norm_tf32<<<NTOK*CCH/256, 256>>>();
    mma_gemm<128,2><<<dim3(256, 4), 256>>>(b_ffn1);
    mma_gemm<512,3><<<dim3(256, 1), 256>>>(b_ffn2);
    reduce_final<<<1, 1024>>>();
    norm_transpose<<<dim3(NTOK/32, CCH/32), 256>>>(out);
}